// round 11
// baseline (speedup 1.0000x reference)
#include <cuda_runtime.h>
#include <cuda_bf16.h>
#include <math.h>
#include <stdint.h>

#define B_SZ    16
#define L_SEQ   4096
#define DM      256
#define NST     32
#define H2      512
#define OUTC    512
#define KDIM    512
#define NTOT    (B_SZ * L_SEQ)          // 65536 positions

#define WHALF   ((size_t)1024 * KDIM)            // offset of W-lo
#define GHALF   ((size_t)NTOT * H2)              // offset of G-lo

// ---------------- helpers ----------------
__device__ __forceinline__ uint32_t smem_u32(const void* p) {
    uint32_t a;
    asm("{ .reg .u64 t; cvta.to.shared.u64 t, %1; cvt.u32.u64 %0, t; }" : "=r"(a) : "l"(p));
    return a;
}
__device__ __forceinline__ void cp_async16(uint32_t s, const void* g) {
    asm volatile("cp.async.cg.shared.global [%0], [%1], 16;" :: "r"(s), "l"(g));
}
#define CP_COMMIT()  asm volatile("cp.async.commit_group;")
#define CP_WAIT(n)   asm volatile("cp.async.wait_group %0;" :: "n"(n))

__device__ __forceinline__ void ldsm4(uint32_t& r0, uint32_t& r1, uint32_t& r2, uint32_t& r3, uint32_t a) {
    asm volatile("ldmatrix.sync.aligned.m8n8.x4.shared.b16 {%0,%1,%2,%3}, [%4];"
                 : "=r"(r0), "=r"(r1), "=r"(r2), "=r"(r3) : "r"(a));
}
__device__ __forceinline__ void mma16816(float* c, const uint32_t* a, uint32_t b0, uint32_t b1) {
    asm volatile("mma.sync.aligned.m16n8k16.row.col.f32.bf16.bf16.f32 "
                 "{%0,%1,%2,%3},{%4,%5,%6,%7},{%8,%9},{%0,%1,%2,%3};"
                 : "+f"(c[0]), "+f"(c[1]), "+f"(c[2]), "+f"(c[3])
                 : "r"(a[0]), "r"(a[1]), "r"(a[2]), "r"(a[3]), "r"(b0), "r"(b1));
}

// ---------------- scratch ----------------
__device__ __align__(1024) float4 g_wc[2][DM][NST];
__device__ __align__(1024) __nv_bfloat16 g_W[2 * 1024 * KDIM];        // [hi | lo], remapped rows
__device__ __align__(1024) __nv_bfloat16 g_G[2 * (size_t)NTOT * H2];  // [hi | lo], acts [pos][ch]

// ---------------- K1: per-mode constants ----------------
__global__ void k_const(const float* __restrict__ ldt_fw, const float* __restrict__ lAr_fw,
                        const float* __restrict__ Ai_fw,  const float* __restrict__ C_fw,
                        const float* __restrict__ ldt_bw, const float* __restrict__ lAr_bw,
                        const float* __restrict__ Ai_bw,  const float* __restrict__ C_bw)
{
    int idx = blockIdx.x * blockDim.x + threadIdx.x;
    int n   = idx & 31;
    int d   = (idx >> 5) & 255;
    int dir = idx >> 13;

    const float* ldt = dir ? ldt_bw : ldt_fw;
    const float* lAr = dir ? lAr_bw : lAr_fw;
    const float* Ai  = dir ? Ai_bw  : Ai_fw;
    const float* C   = dir ? C_bw   : C_fw;

    float dt = expf(ldt[d]);
    float Ar = -expf(lAr[d * 32 + n]);
    float Aim = Ai[d * 32 + n];

    float xr = Ar * dt, xi = Aim * dt;
    float e  = expf(xr);
    float wr = e * cosf(xi);
    float wi = e * sinf(xi);

    float nr = wr - 1.0f, ni = wi;
    float dr = Ar + 1e-8f, di = Aim;
    float den = dr * dr + di * di;
    float rr = (nr * dr + ni * di) / den;
    float ri = (ni * dr - nr * di) / den;

    float Cr  = C[(d * 32 + n) * 2 + 0];
    float Cim = C[(d * 32 + n) * 2 + 1];
    float cr = Cr * rr - Cim * ri;
    float ci = Cr * ri + Cim * rr;

    g_wc[dir][d][n] = make_float4(wr, wi, 2.0f * cr, 2.0f * ci);
}

// ---------------- K1b: W hi/lo split with GLU row remap ----------------
__global__ void k_wsplit(const float* __restrict__ W)
{
    int i = blockIdx.x * blockDim.x + threadIdx.x;   // 0..524287
    int m = i >> 9;
    int k = i & 511;
    int mt = m >> 7, r = m & 127;
    int wrow = (r < 64) ? (mt * 64 + r) : (512 + mt * 64 + r - 64);
    float v = W[(size_t)wrow * KDIM + k];
    __nv_bfloat16 h = __float2bfloat16(v);
    float lo = v - __bfloat162float(h);
    g_W[i] = h;
    g_W[WHALF + i] = __float2bfloat16(lo);
}

// ---------------- K2: bidirectional SSM scan + Dskip; GELU deferred to writeback ----------------
#define TILE_T 64
#define CHB2   32

__global__ void __launch_bounds__(256, 2)
k_scan(const float* __restrict__ x, const float* __restrict__ Dskip)
{
    int b   = blockIdx.x >> 4;            // 0..15
    int dir = (blockIdx.x >> 3) & 1;
    int d0  = (blockIdx.x & 7) * CHB2;    // 8 channel groups of 32

    int tid = threadIdx.x;
    int ch  = tid >> 3;                   // 0..31
    int sub = tid & 7;                    // 0..7 -> 4 modes each
    int d   = d0 + ch;

    __shared__ float su[TILE_T][CHB2];
    __shared__ float sy[TILE_T][CHB2 + 1];   // raw pre-gelu outputs

    float wr[4], wi[4], cr[4], ci[4];
    {
        const float4* wc = &g_wc[dir][d][sub * 4];
#pragma unroll
        for (int i = 0; i < 4; i++) {
            float4 v = wc[i];
            wr[i] = v.x; wi[i] = v.y; cr[i] = v.z; ci[i] = v.w;
        }
    }
    float sre[4], sim[4];
#pragma unroll
    for (int i = 0; i < 4; i++) { sre[i] = 0.f; sim[i] = 0.f; }

    float Dv = Dskip[d];

    const float* xb = x + (size_t)b * L_SEQ * DM + d0;
    size_t rowbase = (size_t)b * L_SEQ;
    int colbase = dir * DM + d0;

    for (int t0 = 0; t0 < L_SEQ; t0 += TILE_T) {
        for (int i = tid; i < TILE_T * CHB2; i += 256) {
            int ll = i >> 5;
            int cc = i & 31;
            int step = t0 + ll;
            int lg = dir ? (L_SEQ - 1 - step) : step;
            su[ll][cc] = xb[(size_t)lg * DM + cc];
        }
        __syncthreads();

#pragma unroll 4
        for (int ll = 0; ll < TILE_T; ll++) {
            float u = su[ll][ch];
            float acc = 0.f;
#pragma unroll
            for (int i = 0; i < 4; i++) {
                float sr_old = sre[i];
                float t = fmaf(wr[i], sr_old, u);
                sre[i] = fmaf(-wi[i], sim[i], t);
                sim[i] = fmaf(wi[i], sr_old, wr[i] * sim[i]);
                acc = fmaf(cr[i], sre[i], acc);
                acc = fmaf(-ci[i], sim[i], acc);
            }
            acc += __shfl_xor_sync(0xffffffffu, acc, 1);
            acc += __shfl_xor_sync(0xffffffffu, acc, 2);
            acc += __shfl_xor_sync(0xffffffffu, acc, 4);
            if (sub == 0) sy[ll][ch] = fmaf(Dv, u, acc);
        }
        __syncthreads();

        for (int i = tid; i < TILE_T * CHB2; i += 256) {
            int cc = i & 31;
            int ll = i >> 5;
            int step = t0 + ll;
            int lg = dir ? (L_SEQ - 1 - step) : step;
            float y = sy[ll][cc];
            float gy = 0.5f * y * (1.0f + erff(y * 0.70710678118654752f));
            __nv_bfloat16 h = __float2bfloat16(gy);
            float lo = gy - __bfloat162float(h);
            size_t idx = (rowbase + lg) * H2 + colbase + cc;
            g_G[idx] = h;
            g_G[GHALF + idx] = __float2bfloat16(lo);
        }
        __syncthreads();
    }
}

// ---------------- K3: mma.sync bf16x3 GEMM + bias + GLU ----------------
// CTA tile M=128 (64 'a' + 64 'b' rows), N=128, K chunks of 64, 3-stage pipeline.
// 512 threads / 16 warps as 4(m) x 4(n); warp tile 32x32.
// MERGED products: per k-step load Ah,Al,Bh,Bl fragments ONCE, issue all 24 MMA
// (AhBh + AhBl + AlBh) against them -> LDSM:MMA = 8:24 instead of 12:24.
#define TILE_BYTES 16384       // 128 rows x 128B (64 bf16 K)
#define BUF_BYTES  (4 * TILE_BYTES)
#define N_STAGE    3
#define DYN_SMEM   (N_STAGE * BUF_BYTES)   // 196608

__global__ void __launch_bounds__(512, 1)
k_gemm_mma(const float* __restrict__ conv_b, float* __restrict__ out)
{
    extern __shared__ char dynsmem[];
    uint32_t sbase = smem_u32(dynsmem);

    int tid  = threadIdx.x;
    int wid  = tid >> 5;
    int lane = tid & 31;
    int mt = blockIdx.x;          // 0..7
    int nt = blockIdx.y;          // 0..511
    int c0 = mt * 64;
    int n0 = nt * 128;

    int wm = wid >> 2;            // 0..3
    int wn = wid & 3;             // 0..3

    const __nv_bfloat16* Abase = g_W + (size_t)(mt * 128) * KDIM;   // hi; lo at +WHALF
    const __nv_bfloat16* Bbase = g_G + (size_t)n0 * KDIM;           // hi; lo at +GHALF

    // ---- chunk loader: 4 tiles x 16KB via cp.async, 512 threads ----
    auto load_chunk = [&](int chunk, int buf) {
        uint32_t sb = sbase + buf * BUF_BYTES;
        int k0 = chunk * 64;
        int row = tid >> 3;          // 0..63 base rows per pass
        int c16 = tid & 7;
#pragma unroll
        for (int i = 0; i < 8; i++) {
            const int tile = i >> 1;           // 0:Ah 1:Al 2:Bh 3:Bl
            int r = (i & 1) * 64 + row;        // 0..127
            uint32_t off = (uint32_t)r * 128 + (uint32_t)c16 * 16;
            uint32_t sw  = off ^ (uint32_t)((r & 7) << 4);
            const __nv_bfloat16* g;
            if      (tile == 0) g = Abase + (size_t)r * KDIM + k0 + c16 * 8;
            else if (tile == 1) g = Abase + WHALF + (size_t)r * KDIM + k0 + c16 * 8;
            else if (tile == 2) g = Bbase + (size_t)r * KDIM + k0 + c16 * 8;
            else                g = Bbase + GHALF + (size_t)r * KDIM + k0 + c16 * 8;
            cp_async16(sb + tile * TILE_BYTES + sw, g);
        }
        CP_COMMIT();
    };

    float acc[2][4][4];
#pragma unroll
    for (int mi = 0; mi < 2; mi++)
#pragma unroll
        for (int nf = 0; nf < 4; nf++)
#pragma unroll
            for (int q = 0; q < 4; q++) acc[mi][nf][q] = 0.f;

    // per-lane ldmatrix address components
    int a_row = wm * 32 + (lane & 15);
    uint32_t a_off = (uint32_t)a_row * 128;
    uint32_t a_x   = (uint32_t)((a_row & 7) << 4);
    uint32_t a_kc  = (uint32_t)((lane >> 4) * 16);

    int b_rl = (lane & 7) + ((lane >> 4) & 1) * 8;        // row within 16-row group
    uint32_t b_kc = (uint32_t)(((lane >> 3) & 1) * 16);
    int br0 = wn * 32 + b_rl;
    int br1 = wn * 32 + 16 + b_rl;
    uint32_t b_off0 = (uint32_t)br0 * 128;
    uint32_t b_x0   = (uint32_t)((br0 & 7) << 4);
    uint32_t b_off1 = (uint32_t)br1 * 128;
    uint32_t b_x1   = (uint32_t)((br1 & 7) << 4);

    load_chunk(0, 0);
    load_chunk(1, 1);

#pragma unroll 1
    for (int c = 0; c < 8; c++) {
        int buf = c % N_STAGE;
        CP_WAIT(1);                       // chunk c complete (c+1 may be in flight)
        __syncthreads();
        if (c + 2 < 8) load_chunk(c + 2, (c + 2) % N_STAGE);

        uint32_t sb  = sbase + buf * BUF_BYTES;

#pragma unroll
        for (int ks = 0; ks < 4; ks++) {
            uint32_t kc = (uint32_t)(ks * 32);
            uint32_t ac = kc + a_kc;
            uint32_t bc = kc + b_kc;

            // load ALL fragments for this k-step once
            uint32_t ah[8], al[8], bh[8], bl[8];
            {
                uint32_t A0 = sb + a_off + (ac ^ a_x);                    // Ah tile
                ldsm4(ah[0], ah[1], ah[2], ah[3], A0);
                ldsm4(ah[4], ah[5], ah[6], ah[7], A0 + 16 * 128);
                uint32_t B0 = sb + 2 * TILE_BYTES + b_off0 + (bc ^ b_x0); // Bh tile
                ldsm4(bh[0], bh[1], bh[2], bh[3], B0);
                uint32_t B1 = sb + 2 * TILE_BYTES + b_off1 + (bc ^ b_x1);
                ldsm4(bh[4], bh[5], bh[6], bh[7], B1);
                uint32_t A1 = sb + TILE_BYTES + a_off + (ac ^ a_x);       // Al tile
                ldsm4(al[0], al[1], al[2], al[3], A1);
                ldsm4(al[4], al[5], al[6], al[7], A1 + 16 * 128);
                uint32_t B2 = sb + 3 * TILE_BYTES + b_off0 + (bc ^ b_x0); // Bl tile
                ldsm4(bl[0], bl[1], bl[2], bl[3], B2);
                uint32_t B3 = sb + 3 * TILE_BYTES + b_off1 + (bc ^ b_x1);
                ldsm4(bl[4], bl[5], bl[6], bl[7], B3);
            }

            // 24 MMAs reusing the 4 fragment sets
#pragma unroll
            for (int nf = 0; nf < 4; nf++) {
                mma16816(acc[0][nf], ah,     bh[nf * 2], bh[nf * 2 + 1]);
                mma16816(acc[1][nf], ah + 4, bh[nf * 2], bh[nf * 2 + 1]);
            }
#pragma unroll
            for (int nf = 0; nf < 4; nf++) {
                mma16816(acc[0][nf], ah,     bl[nf * 2], bl[nf * 2 + 1]);
                mma16816(acc[1][nf], ah + 4, bl[nf * 2], bl[nf * 2 + 1]);
            }
#pragma unroll
            for (int nf = 0; nf < 4; nf++) {
                mma16816(acc[0][nf], al,     bh[nf * 2], bh[nf * 2 + 1]);
                mma16816(acc[1][nf], al + 4, bh[nf * 2], bh[nf * 2 + 1]);
            }
        }
    }
    __syncthreads();

    // ---- epilogue: bias -> stage smem -> GLU -> coalesced store ----
    float* stage = (float*)dynsmem;          // [128][133]
    float bias_r[4];
#pragma unroll
    for (int q = 0; q < 4; q++) {
        int m = wm * 32 + q * 8 + (lane >> 2);
        bias_r[q] = (m < 64) ? conv_b[c0 + m] : conv_b[512 + c0 + m - 64];
    }

#pragma unroll
    for (int mi = 0; mi < 2; mi++) {
        int m = wm * 32 + mi * 16 + (lane >> 2);
#pragma unroll
        for (int nf = 0; nf < 4; nf++) {
            int n = wn * 32 + nf * 8 + 2 * (lane & 3);
            stage[m * 133 + n]           = acc[mi][nf][0] + bias_r[mi * 2];
            stage[m * 133 + n + 1]       = acc[mi][nf][1] + bias_r[mi * 2];
            stage[(m + 8) * 133 + n]     = acc[mi][nf][2] + bias_r[mi * 2 + 1];
            stage[(m + 8) * 133 + n + 1] = acc[mi][nf][3] + bias_r[mi * 2 + 1];
        }
    }
    __syncthreads();

    for (int i = tid; i < 128 * 64; i += 512) {
        int n  = i >> 6;
        int ch = i & 63;
        float a  = stage[ch * 133 + n];
        float bb = stage[(ch + 64) * 133 + n];
        float r = a / (1.0f + expf(-bb));
        out[(size_t)(n0 + n) * OUTC + c0 + ch] = r;
    }
}

// ---------------- K4: LayerNorm ----------------
__global__ void __launch_bounds__(128)
k_ln(float* __restrict__ out, const float* __restrict__ gamma, const float* __restrict__ beta)
{
    int tid = threadIdx.x;
    float* row = out + (size_t)blockIdx.x * OUTC;
    float4 v = reinterpret_cast<float4*>(row)[tid];

    __shared__ float red[8];

    float s = v.x + v.y + v.z + v.w;
#pragma unroll
    for (int o = 16; o; o >>= 1) s += __shfl_xor_sync(0xffffffffu, s, o);
    if ((tid & 31) == 0) red[tid >> 5] = s;
    __syncthreads();
    float mu = (red[0] + red[1] + red[2] + red[3]) * (1.0f / OUTC);

    float dx = v.x - mu, dy = v.y - mu, dz = v.z - mu, dw = v.w - mu;
    float sq = dx * dx + dy * dy + dz * dz + dw * dw;
#pragma unroll
    for (int o = 16; o; o >>= 1) sq += __shfl_xor_sync(0xffffffffu, sq, o);
    if ((tid & 31) == 0) red[4 + (tid >> 5)] = sq;
    __syncthreads();
    float var = (red[4] + red[5] + red[6] + red[7]) * (1.0f / OUTC);
    float inv = rsqrtf(var + 1e-5f);

    float4 g4 = reinterpret_cast<const float4*>(gamma)[tid];
    float4 b4 = reinterpret_cast<const float4*>(beta)[tid];
    float4 o;
    o.x = dx * inv * g4.x + b4.x;
    o.y = dy * inv * g4.y + b4.y;
    o.z = dz * inv * g4.z + b4.z;
    o.w = dw * inv * g4.w + b4.w;
    reinterpret_cast<float4*>(row)[tid] = o;
}

// ---------------- launch ----------------
extern "C" void kernel_launch(void* const* d_in, const int* in_sizes, int n_in,
                              void* d_out, int out_size)
{
    const float* x       = (const float*)d_in[0];
    const float* ldt_fw  = (const float*)d_in[1];
    const float* lAr_fw  = (const float*)d_in[2];
    const float* Ai_fw   = (const float*)d_in[3];
    const float* C_fw    = (const float*)d_in[4];
    const float* ldt_bw  = (const float*)d_in[5];
    const float* lAr_bw  = (const float*)d_in[6];
    const float* Ai_bw   = (const float*)d_in[7];
    const float* C_bw    = (const float*)d_in[8];
    const float* Dskip   = (const float*)d_in[9];
    const float* conv_w  = (const float*)d_in[10];
    const float* conv_b  = (const float*)d_in[11];
    const float* ln_g    = (const float*)d_in[12];
    const float* ln_b    = (const float*)d_in[13];
    float* out = (float*)d_out;

    cudaFuncSetAttribute((const void*)k_gemm_mma,
                         cudaFuncAttributeMaxDynamicSharedMemorySize, DYN_SMEM);

    k_const<<<64, 256>>>(ldt_fw, lAr_fw, Ai_fw, C_fw, ldt_bw, lAr_bw, Ai_bw, C_bw);
    k_wsplit<<<2048, 256>>>(conv_w);
    k_scan<<<256, 256>>>(x, Dskip);
    dim3 g3(8, 512);
    k_gemm_mma<<<g3, 512, DYN_SMEM>>>(conv_b, out);
    k_ln<<<B_SZ * L_SEQ, 128>>>(out, ln_g, ln_b);
}

// round 12
// speedup vs baseline: 1.0042x; 1.0042x over previous
#include <cuda_runtime.h>
#include <cuda_bf16.h>
#include <math.h>
#include <stdint.h>

#define B_SZ    16
#define L_SEQ   4096
#define DM      256
#define NST     32
#define H2      512
#define OUTC    512
#define KDIM    512
#define NTOT    (B_SZ * L_SEQ)          // 65536 positions

#define WHALF   ((size_t)1024 * KDIM)            // offset of W-lo
#define GHALF   ((size_t)NTOT * H2)              // offset of G-lo

// ---------------- helpers ----------------
__device__ __forceinline__ uint32_t smem_u32(const void* p) {
    uint32_t a;
    asm("{ .reg .u64 t; cvta.to.shared.u64 t, %1; cvt.u32.u64 %0, t; }" : "=r"(a) : "l"(p));
    return a;
}
__device__ __forceinline__ void cp_async16(uint32_t s, const void* g) {
    asm volatile("cp.async.cg.shared.global [%0], [%1], 16;" :: "r"(s), "l"(g));
}
#define CP_COMMIT()  asm volatile("cp.async.commit_group;")
#define CP_WAIT(n)   asm volatile("cp.async.wait_group %0;" :: "n"(n))

__device__ __forceinline__ void ldsm4(uint32_t& r0, uint32_t& r1, uint32_t& r2, uint32_t& r3, uint32_t a) {
    asm volatile("ldmatrix.sync.aligned.m8n8.x4.shared.b16 {%0,%1,%2,%3}, [%4];"
                 : "=r"(r0), "=r"(r1), "=r"(r2), "=r"(r3) : "r"(a));
}
__device__ __forceinline__ void mma16816(float* c, const uint32_t* a, uint32_t b0, uint32_t b1) {
    asm volatile("mma.sync.aligned.m16n8k16.row.col.f32.bf16.bf16.f32 "
                 "{%0,%1,%2,%3},{%4,%5,%6,%7},{%8,%9},{%0,%1,%2,%3};"
                 : "+f"(c[0]), "+f"(c[1]), "+f"(c[2]), "+f"(c[3])
                 : "r"(a[0]), "r"(a[1]), "r"(a[2]), "r"(a[3]), "r"(b0), "r"(b1));
}

// ---------------- scratch ----------------
__device__ __align__(1024) float4 g_wc[2][DM][NST];
__device__ __align__(1024) __nv_bfloat16 g_W[2 * 1024 * KDIM];        // [hi | lo], remapped rows
__device__ __align__(1024) __nv_bfloat16 g_G[2 * (size_t)NTOT * H2];  // [hi | lo], acts [pos][ch]

// ---------------- K1: per-mode constants ----------------
__global__ void k_const(const float* __restrict__ ldt_fw, const float* __restrict__ lAr_fw,
                        const float* __restrict__ Ai_fw,  const float* __restrict__ C_fw,
                        const float* __restrict__ ldt_bw, const float* __restrict__ lAr_bw,
                        const float* __restrict__ Ai_bw,  const float* __restrict__ C_bw)
{
    int idx = blockIdx.x * blockDim.x + threadIdx.x;
    int n   = idx & 31;
    int d   = (idx >> 5) & 255;
    int dir = idx >> 13;

    const float* ldt = dir ? ldt_bw : ldt_fw;
    const float* lAr = dir ? lAr_bw : lAr_fw;
    const float* Ai  = dir ? Ai_bw  : Ai_fw;
    const float* C   = dir ? C_bw   : C_fw;

    float dt = expf(ldt[d]);
    float Ar = -expf(lAr[d * 32 + n]);
    float Aim = Ai[d * 32 + n];

    float xr = Ar * dt, xi = Aim * dt;
    float e  = expf(xr);
    float wr = e * cosf(xi);
    float wi = e * sinf(xi);

    float nr = wr - 1.0f, ni = wi;
    float dr = Ar + 1e-8f, di = Aim;
    float den = dr * dr + di * di;
    float rr = (nr * dr + ni * di) / den;
    float ri = (ni * dr - nr * di) / den;

    float Cr  = C[(d * 32 + n) * 2 + 0];
    float Cim = C[(d * 32 + n) * 2 + 1];
    float cr = Cr * rr - Cim * ri;
    float ci = Cr * ri + Cim * rr;

    g_wc[dir][d][n] = make_float4(wr, wi, 2.0f * cr, 2.0f * ci);
}

// ---------------- K1b: W hi/lo split with GLU row remap ----------------
__global__ void k_wsplit(const float* __restrict__ W)
{
    int i = blockIdx.x * blockDim.x + threadIdx.x;   // 0..524287
    int m = i >> 9;
    int k = i & 511;
    int mt = m >> 7, r = m & 127;
    int wrow = (r < 64) ? (mt * 64 + r) : (512 + mt * 64 + r - 64);
    float v = W[(size_t)wrow * KDIM + k];
    __nv_bfloat16 h = __float2bfloat16(v);
    float lo = v - __bfloat162float(h);
    g_W[i] = h;
    g_W[WHALF + i] = __float2bfloat16(lo);
}

// ---------------- K2: bidirectional SSM scan + Dskip; GELU deferred to writeback ----------------
#define TILE_T 64
#define CHB2   32

__global__ void __launch_bounds__(256, 2)
k_scan(const float* __restrict__ x, const float* __restrict__ Dskip)
{
    int b   = blockIdx.x >> 4;            // 0..15
    int dir = (blockIdx.x >> 3) & 1;
    int d0  = (blockIdx.x & 7) * CHB2;    // 8 channel groups of 32

    int tid = threadIdx.x;
    int ch  = tid >> 3;                   // 0..31
    int sub = tid & 7;                    // 0..7 -> 4 modes each
    int d   = d0 + ch;

    __shared__ float su[TILE_T][CHB2];
    __shared__ float sy[TILE_T][CHB2 + 1];   // raw pre-gelu outputs

    float wr[4], wi[4], cr[4], ci[4];
    {
        const float4* wc = &g_wc[dir][d][sub * 4];
#pragma unroll
        for (int i = 0; i < 4; i++) {
            float4 v = wc[i];
            wr[i] = v.x; wi[i] = v.y; cr[i] = v.z; ci[i] = v.w;
        }
    }
    float sre[4], sim[4];
#pragma unroll
    for (int i = 0; i < 4; i++) { sre[i] = 0.f; sim[i] = 0.f; }

    float Dv = Dskip[d];

    const float* xb = x + (size_t)b * L_SEQ * DM + d0;
    size_t rowbase = (size_t)b * L_SEQ;
    int colbase = dir * DM + d0;

    for (int t0 = 0; t0 < L_SEQ; t0 += TILE_T) {
        for (int i = tid; i < TILE_T * CHB2; i += 256) {
            int ll = i >> 5;
            int cc = i & 31;
            int step = t0 + ll;
            int lg = dir ? (L_SEQ - 1 - step) : step;
            su[ll][cc] = xb[(size_t)lg * DM + cc];
        }
        __syncthreads();

#pragma unroll 4
        for (int ll = 0; ll < TILE_T; ll++) {
            float u = su[ll][ch];
            float acc = 0.f;
#pragma unroll
            for (int i = 0; i < 4; i++) {
                float sr_old = sre[i];
                float t = fmaf(wr[i], sr_old, u);
                sre[i] = fmaf(-wi[i], sim[i], t);
                sim[i] = fmaf(wi[i], sr_old, wr[i] * sim[i]);
                acc = fmaf(cr[i], sre[i], acc);
                acc = fmaf(-ci[i], sim[i], acc);
            }
            acc += __shfl_xor_sync(0xffffffffu, acc, 1);
            acc += __shfl_xor_sync(0xffffffffu, acc, 2);
            acc += __shfl_xor_sync(0xffffffffu, acc, 4);
            if (sub == 0) sy[ll][ch] = fmaf(Dv, u, acc);
        }
        __syncthreads();

        for (int i = tid; i < TILE_T * CHB2; i += 256) {
            int cc = i & 31;
            int ll = i >> 5;
            int step = t0 + ll;
            int lg = dir ? (L_SEQ - 1 - step) : step;
            float y = sy[ll][cc];
            float gy = 0.5f * y * (1.0f + erff(y * 0.70710678118654752f));
            __nv_bfloat16 h = __float2bfloat16(gy);
            float lo = gy - __bfloat162float(h);
            size_t idx = (rowbase + lg) * H2 + colbase + cc;
            g_G[idx] = h;
            g_G[GHALF + idx] = __float2bfloat16(lo);
        }
        __syncthreads();
    }
}

// ---------------- K3: mma.sync bf16x3 GEMM + bias + GLU ----------------
// CTA tile M=128 (64 'a' + 64 'b' rows), N=128, K chunks of 64, 3-stage pipeline.
// 512 threads / 16 warps as 4(m) x 4(n); warp tile 32x32.
// MERGED products: per k-step load Ah,Al,Bh,Bl fragments ONCE, issue all 24 MMA
// (AhBh + AhBl + AlBh) against them -> LDSM:MMA = 8:24 instead of 12:24.
#define TILE_BYTES 16384       // 128 rows x 128B (64 bf16 K)
#define BUF_BYTES  (4 * TILE_BYTES)
#define N_STAGE    3
#define DYN_SMEM   (N_STAGE * BUF_BYTES)   // 196608

__global__ void __launch_bounds__(512, 1)
k_gemm_mma(const float* __restrict__ conv_b, float* __restrict__ out)
{
    extern __shared__ char dynsmem[];
    uint32_t sbase = smem_u32(dynsmem);

    int tid  = threadIdx.x;
    int wid  = tid >> 5;
    int lane = tid & 31;
    int mt = blockIdx.x;          // 0..7
    int nt = blockIdx.y;          // 0..511
    int c0 = mt * 64;
    int n0 = nt * 128;

    int wm = wid >> 2;            // 0..3
    int wn = wid & 3;             // 0..3

    const __nv_bfloat16* Abase = g_W + (size_t)(mt * 128) * KDIM;   // hi; lo at +WHALF
    const __nv_bfloat16* Bbase = g_G + (size_t)n0 * KDIM;           // hi; lo at +GHALF

    // ---- chunk loader: 4 tiles x 16KB via cp.async, 512 threads ----
    auto load_chunk = [&](int chunk, int buf) {
        uint32_t sb = sbase + buf * BUF_BYTES;
        int k0 = chunk * 64;
        int row = tid >> 3;          // 0..63 base rows per pass
        int c16 = tid & 7;
#pragma unroll
        for (int i = 0; i < 8; i++) {
            const int tile = i >> 1;           // 0:Ah 1:Al 2:Bh 3:Bl
            int r = (i & 1) * 64 + row;        // 0..127
            uint32_t off = (uint32_t)r * 128 + (uint32_t)c16 * 16;
            uint32_t sw  = off ^ (uint32_t)((r & 7) << 4);
            const __nv_bfloat16* g;
            if      (tile == 0) g = Abase + (size_t)r * KDIM + k0 + c16 * 8;
            else if (tile == 1) g = Abase + WHALF + (size_t)r * KDIM + k0 + c16 * 8;
            else if (tile == 2) g = Bbase + (size_t)r * KDIM + k0 + c16 * 8;
            else                g = Bbase + GHALF + (size_t)r * KDIM + k0 + c16 * 8;
            cp_async16(sb + tile * TILE_BYTES + sw, g);
        }
        CP_COMMIT();
    };

    float acc[2][4][4];
#pragma unroll
    for (int mi = 0; mi < 2; mi++)
#pragma unroll
        for (int nf = 0; nf < 4; nf++)
#pragma unroll
            for (int q = 0; q < 4; q++) acc[mi][nf][q] = 0.f;

    // per-lane ldmatrix address components
    int a_row = wm * 32 + (lane & 15);
    uint32_t a_off = (uint32_t)a_row * 128;
    uint32_t a_x   = (uint32_t)((a_row & 7) << 4);
    uint32_t a_kc  = (uint32_t)((lane >> 4) * 16);

    int b_rl = (lane & 7) + ((lane >> 4) & 1) * 8;        // row within 16-row group
    uint32_t b_kc = (uint32_t)(((lane >> 3) & 1) * 16);
    int br0 = wn * 32 + b_rl;
    int br1 = wn * 32 + 16 + b_rl;
    uint32_t b_off0 = (uint32_t)br0 * 128;
    uint32_t b_x0   = (uint32_t)((br0 & 7) << 4);
    uint32_t b_off1 = (uint32_t)br1 * 128;
    uint32_t b_x1   = (uint32_t)((br1 & 7) << 4);

    load_chunk(0, 0);
    load_chunk(1, 1);

#pragma unroll 1
    for (int c = 0; c < 8; c++) {
        int buf = c % N_STAGE;
        CP_WAIT(1);                       // chunk c complete (c+1 may be in flight)
        __syncthreads();
        if (c + 2 < 8) load_chunk(c + 2, (c + 2) % N_STAGE);

        uint32_t sb  = sbase + buf * BUF_BYTES;

#pragma unroll
        for (int ks = 0; ks < 4; ks++) {
            uint32_t kc = (uint32_t)(ks * 32);
            uint32_t ac = kc + a_kc;
            uint32_t bc = kc + b_kc;

            // load ALL fragments for this k-step once
            uint32_t ah[8], al[8], bh[8], bl[8];
            {
                uint32_t A0 = sb + a_off + (ac ^ a_x);                    // Ah tile
                ldsm4(ah[0], ah[1], ah[2], ah[3], A0);
                ldsm4(ah[4], ah[5], ah[6], ah[7], A0 + 16 * 128);
                uint32_t B0 = sb + 2 * TILE_BYTES + b_off0 + (bc ^ b_x0); // Bh tile
                ldsm4(bh[0], bh[1], bh[2], bh[3], B0);
                uint32_t B1 = sb + 2 * TILE_BYTES + b_off1 + (bc ^ b_x1);
                ldsm4(bh[4], bh[5], bh[6], bh[7], B1);
                uint32_t A1 = sb + TILE_BYTES + a_off + (ac ^ a_x);       // Al tile
                ldsm4(al[0], al[1], al[2], al[3], A1);
                ldsm4(al[4], al[5], al[6], al[7], A1 + 16 * 128);
                uint32_t B2 = sb + 3 * TILE_BYTES + b_off0 + (bc ^ b_x0); // Bl tile
                ldsm4(bl[0], bl[1], bl[2], bl[3], B2);
                uint32_t B3 = sb + 3 * TILE_BYTES + b_off1 + (bc ^ b_x1);
                ldsm4(bl[4], bl[5], bl[6], bl[7], B3);
            }

            // 24 MMAs reusing the 4 fragment sets
#pragma unroll
            for (int nf = 0; nf < 4; nf++) {
                mma16816(acc[0][nf], ah,     bh[nf * 2], bh[nf * 2 + 1]);
                mma16816(acc[1][nf], ah + 4, bh[nf * 2], bh[nf * 2 + 1]);
            }
#pragma unroll
            for (int nf = 0; nf < 4; nf++) {
                mma16816(acc[0][nf], ah,     bl[nf * 2], bl[nf * 2 + 1]);
                mma16816(acc[1][nf], ah + 4, bl[nf * 2], bl[nf * 2 + 1]);
            }
#pragma unroll
            for (int nf = 0; nf < 4; nf++) {
                mma16816(acc[0][nf], al,     bh[nf * 2], bh[nf * 2 + 1]);
                mma16816(acc[1][nf], al + 4, bh[nf * 2], bh[nf * 2 + 1]);
            }
        }
    }
    __syncthreads();

    // ---- epilogue: bias -> stage smem -> GLU -> coalesced store ----
    float* stage = (float*)dynsmem;          // [128][133]
    float bias_r[4];
#pragma unroll
    for (int q = 0; q < 4; q++) {
        int m = wm * 32 + q * 8 + (lane >> 2);
        bias_r[q] = (m < 64) ? conv_b[c0 + m] : conv_b[512 + c0 + m - 64];
    }

#pragma unroll
    for (int mi = 0; mi < 2; mi++) {
        int m = wm * 32 + mi * 16 + (lane >> 2);
#pragma unroll
        for (int nf = 0; nf < 4; nf++) {
            int n = wn * 32 + nf * 8 + 2 * (lane & 3);
            stage[m * 133 + n]           = acc[mi][nf][0] + bias_r[mi * 2];
            stage[m * 133 + n + 1]       = acc[mi][nf][1] + bias_r[mi * 2];
            stage[(m + 8) * 133 + n]     = acc[mi][nf][2] + bias_r[mi * 2 + 1];
            stage[(m + 8) * 133 + n + 1] = acc[mi][nf][3] + bias_r[mi * 2 + 1];
        }
    }
    __syncthreads();

    for (int i = tid; i < 128 * 64; i += 512) {
        int n  = i >> 6;
        int ch = i & 63;
        float a  = stage[ch * 133 + n];
        float bb = stage[(ch + 64) * 133 + n];
        float r = a / (1.0f + expf(-bb));
        out[(size_t)(n0 + n) * OUTC + c0 + ch] = r;
    }
}

// ---------------- K4: LayerNorm ----------------
__global__ void __launch_bounds__(128)
k_ln(float* __restrict__ out, const float* __restrict__ gamma, const float* __restrict__ beta)
{
    int tid = threadIdx.x;
    float* row = out + (size_t)blockIdx.x * OUTC;
    float4 v = reinterpret_cast<float4*>(row)[tid];

    __shared__ float red[8];

    float s = v.x + v.y + v.z + v.w;
#pragma unroll
    for (int o = 16; o; o >>= 1) s += __shfl_xor_sync(0xffffffffu, s, o);
    if ((tid & 31) == 0) red[tid >> 5] = s;
    __syncthreads();
    float mu = (red[0] + red[1] + red[2] + red[3]) * (1.0f / OUTC);

    float dx = v.x - mu, dy = v.y - mu, dz = v.z - mu, dw = v.w - mu;
    float sq = dx * dx + dy * dy + dz * dz + dw * dw;
#pragma unroll
    for (int o = 16; o; o >>= 1) sq += __shfl_xor_sync(0xffffffffu, sq, o);
    if ((tid & 31) == 0) red[4 + (tid >> 5)] = sq;
    __syncthreads();
    float var = (red[4] + red[5] + red[6] + red[7]) * (1.0f / OUTC);
    float inv = rsqrtf(var + 1e-5f);

    float4 g4 = reinterpret_cast<const float4*>(gamma)[tid];
    float4 b4 = reinterpret_cast<const float4*>(beta)[tid];
    float4 o;
    o.x = dx * inv * g4.x + b4.x;
    o.y = dy * inv * g4.y + b4.y;
    o.z = dz * inv * g4.z + b4.z;
    o.w = dw * inv * g4.w + b4.w;
    reinterpret_cast<float4*>(row)[tid] = o;
}

// ---------------- launch ----------------
extern "C" void kernel_launch(void* const* d_in, const int* in_sizes, int n_in,
                              void* d_out, int out_size)
{
    const float* x       = (const float*)d_in[0];
    const float* ldt_fw  = (const float*)d_in[1];
    const float* lAr_fw  = (const float*)d_in[2];
    const float* Ai_fw   = (const float*)d_in[3];
    const float* C_fw    = (const float*)d_in[4];
    const float* ldt_bw  = (const float*)d_in[5];
    const float* lAr_bw  = (const float*)d_in[6];
    const float* Ai_bw   = (const float*)d_in[7];
    const float* C_bw    = (const float*)d_in[8];
    const float* Dskip   = (const float*)d_in[9];
    const float* conv_w  = (const float*)d_in[10];
    const float* conv_b  = (const float*)d_in[11];
    const float* ln_g    = (const float*)d_in[12];
    const float* ln_b    = (const float*)d_in[13];
    float* out = (float*)d_out;

    cudaFuncSetAttribute((const void*)k_gemm_mma,
                         cudaFuncAttributeMaxDynamicSharedMemorySize, DYN_SMEM);

    k_const<<<64, 256>>>(ldt_fw, lAr_fw, Ai_fw, C_fw, ldt_bw, lAr_bw, Ai_bw, C_bw);
    k_wsplit<<<2048, 256>>>(conv_w);
    k_scan<<<256, 256>>>(x, Dskip);
    dim3 g3(8, 512);
    k_gemm_mma<<<g3, 512, DYN_SMEM>>>(conv_b, out);
    k_ln<<<B_SZ * L_SEQ, 128>>>(out, ln_g, ln_b);
}